// round 7
// baseline (speedup 1.0000x reference)
#include <cuda_runtime.h>

#define BB 2
#define NN 262144
#define SS 24
#define TOT (BB*NN)
#define EPSV 1e-4f
#define PAD 257

// ---- scratch (no allocation; __device__ globals, zero-initialized at load).
// Invariant: g_u, g_sums, g_done are zero at entry of every execution —
// true at first call (static init) and restored at the end of gather_y.
__device__ float g_wm[TOT];
__device__ float g_u[TOT];
__device__ float g_v[TOT];
__device__ double g_sums[3];   // [0]=sum|A|, [1]=sum(valid), [2]=sum(diff^2)
__device__ unsigned g_done;

// ---------------------------------------------------------------------------
__device__ __forceinline__ float blockReduceSum(float v, float* sh) {
    int lane = threadIdx.x & 31;
    int wid  = threadIdx.x >> 5;
    #pragma unroll
    for (int o = 16; o > 0; o >>= 1) v += __shfl_down_sync(0xffffffffu, v, o);
    if (lane == 0) sh[wid] = v;
    __syncthreads();
    v = (threadIdx.x < 8) ? sh[threadIdx.x] : 0.f;
    if (wid == 0) {
        #pragma unroll
        for (int o = 4; o > 0; o >>= 1) v += __shfl_down_sync(0xffffffffu, v, o);
    }
    return v;
}

__device__ __forceinline__ void load_nbr24(const int* __restrict__ nbr,
                                           long long i, int* nn) {
    const int4* nb4 = (const int4*)(nbr + i * SS);
    #pragma unroll
    for (int k = 0; k < 6; k++) {
        int4 q = nb4[k];
        nn[4*k+0] = q.x; nn[4*k+1] = q.y; nn[4*k+2] = q.z; nn[4*k+3] = q.w;
    }
}

__device__ __forceinline__ void stage25(const float* __restrict__ src,
                                        int node0, float* sh_g, int tid) {
    const float* gBase = src + (long long)node0 * 25;
    #pragma unroll
    for (int k = 0; k < 25; k++) {
        int t = k * 256 + tid;
        sh_g[(t % 25) * PAD + t / 25] = gBase[t];
    }
}

// ---------------------------------------------------------------------------
// K1: fused init + scatter.
// wm = w*vm ; u = wm*G0 + G^T-scatter (25 atomics/node into zero g_u) ;
// flat |A| + valid reductions (streaming, hides under atomic floor).
__global__ __launch_bounds__(256) void k_scatter_init(const float* __restrict__ G,
                                                      const float* __restrict__ Ad,
                                                      const float* __restrict__ Ao,
                                                      const float* __restrict__ w,
                                                      const float* __restrict__ vm,
                                                      const int* __restrict__ nbr) {
    __shared__ float sh_g[25 * PAD];
    __shared__ float sh_red[8];
    int tid = threadIdx.x;
    int node0 = blockIdx.x * 256;
    long long i = node0 + tid;
    int base = (i >= NN) ? NN : 0;

    stage25(G, node0, sh_g, tid);
    __syncthreads();

    float v   = vm[i];
    float wmv = w[i] * v;
    g_wm[i] = wmv;

    int nn[24];
    load_nbr24(nbr, i, nn);

    atomicAdd(&g_u[i], wmv * sh_g[tid]);              // diagonal term
    #pragma unroll
    for (int j = 0; j < SS; j++) {
        int nb = nn[j];
        if ((unsigned)nb < (unsigned)NN)
            atomicAdd(&g_u[base + nb], wmv * sh_g[(j + 1) * PAD + tid]);
    }

    // flat |A| partial (any bijection over Ao works for a global sum)
    float s = fabsf(Ad[i]);
    const float4* A4 = (const float4*)Ao;             // TOT*6 float4 total
    #pragma unroll
    for (int k = 0; k < 6; k++) {
        float4 a = A4[(long long)k * TOT + i];
        s += fabsf(a.x) + fabsf(a.y) + fabsf(a.z) + fabsf(a.w);
    }
    float ba = blockReduceSum(s, sh_red);
    if (tid == 0) atomicAdd(&g_sums[0], (double)ba);
    __syncthreads();
    float bv = blockReduceSum(v, sh_red);
    if (tid == 0) atomicAdd(&g_sums[1], (double)bv);
}

// K2: v = G u + eps*wm (smem-staged coefficients, batched random gathers)
__global__ __launch_bounds__(256) void k_gather_v(const float* __restrict__ G,
                                                  const int* __restrict__ nbr) {
    __shared__ float sh_g[25 * PAD];
    int tid = threadIdx.x;
    int node0 = blockIdx.x * 256;
    long long i = node0 + tid;
    int base = (i >= NN) ? NN : 0;

    stage25(G, node0, sh_g, tid);
    __syncthreads();

    int nn[24];
    load_nbr24(nbr, i, nn);
    float xs[24];
    #pragma unroll
    for (int j = 0; j < SS; j++)
        xs[j] = ((unsigned)nn[j] < (unsigned)NN) ? g_u[base + nn[j]] : 0.f;

    float acc = g_u[i] * sh_g[tid];
    #pragma unroll
    for (int j = 0; j < SS; j++)
        acc = fmaf(xs[j], sh_g[(j + 1) * PAD + tid], acc);

    g_v[i] = acc + EPSV * g_wm[i];
}

// K3: y = A v ; z = y/norm ; diff^2 reduction ; reset g_u ;
//     last block finalizes out and resets g_sums/g_done for next replay.
__global__ __launch_bounds__(256) void k_gather_y(const float* __restrict__ Ad,
                                                  const float* __restrict__ Ao,
                                                  const float* __restrict__ vm,
                                                  const int* __restrict__ nbr,
                                                  float* __restrict__ out) {
    __shared__ float sh_a[24 * PAD];
    __shared__ float sh_red[8];
    __shared__ float s_inv;
    int tid = threadIdx.x;
    int node0 = blockIdx.x * 256;
    long long i = node0 + tid;
    int base = (i >= NN) ? NN : 0;

    const float* aBase = Ao + (long long)node0 * SS;
    #pragma unroll
    for (int k = 0; k < 24; k++) {
        int t = k * 256 + tid;
        sh_a[(t % 24) * PAD + t / 24] = aBase[t];
    }
    if (tid == 0) {
        double norm = g_sums[0] / (g_sums[1] * 25.0 + 1e-6);
        s_inv = (float)(1.0 / (norm + 1e-8));
    }
    __syncthreads();

    int nn[24];
    load_nbr24(nbr, i, nn);
    float xs[24];
    #pragma unroll
    for (int j = 0; j < SS; j++)
        xs[j] = ((unsigned)nn[j] < (unsigned)NN) ? g_v[base + nn[j]] : 0.f;

    float acc = g_v[i] * Ad[i];
    #pragma unroll
    for (int j = 0; j < SS; j++)
        acc = fmaf(xs[j], sh_a[j * PAD + tid], acc);

    float z = acc * s_inv;
    float d = (z - g_wm[i]) * vm[i];
    float sred = blockReduceSum(d * d, sh_red);
    if (tid == 0) atomicAdd(&g_sums[2], (double)sred);

    g_u[i] = 0.f;                       // restore zero-invariant for next replay

    // last-block finalize (threadFenceReduction pattern)
    if (tid == 0) {
        __threadfence();
        unsigned prev = atomicAdd(&g_done, 1u);
        if (prev == gridDim.x - 1) {
            double s2 = *((volatile double*)&g_sums[2]);
            double s1 = *((volatile double*)&g_sums[1]);
            out[0] = (float)(s2 / (s1 + 1e-6));
            g_sums[0] = 0.0; g_sums[1] = 0.0; g_sums[2] = 0.0;
            g_done = 0u;
        }
    }
}

// ---------------------------------------------------------------------------
extern "C" void kernel_launch(void* const* d_in, const int* in_sizes, int n_in,
                              void* d_out, int out_size) {
    const float* G   = (const float*)d_in[0];   // [2,N,25]
    const float* Ad  = (const float*)d_in[1];   // [2,N,1]
    const float* Ao  = (const float*)d_in[2];   // [2,N,24]
    const float* w   = (const float*)d_in[3];   // [2,N,1]
    const float* vm  = (const float*)d_in[4];   // [2,N,1]
    const int*   nbr = (const int*)d_in[5];     // [2,N,24] int32
    float* out = (float*)d_out;

    const int T = 256;
    const int nodeBlocks = TOT / T;             // 2048, exact

    k_scatter_init<<<nodeBlocks, T>>>(G, Ad, Ao, w, vm, nbr);
    k_gather_v    <<<nodeBlocks, T>>>(G, nbr);
    k_gather_y    <<<nodeBlocks, T>>>(Ad, Ao, vm, nbr, out);
}

// round 8
// speedup vs baseline: 1.4282x; 1.4282x over previous
#include <cuda_runtime.h>

#define BB 2
#define NN 262144
#define SS 24
#define TOT (BB*NN)
#define EPSV 1e-4f
#define PAD 257

// ---- scratch (no allocation allowed; __device__ globals) ----
__device__ float g_wm[TOT];
__device__ float g_u[TOT];
__device__ float g_v[TOT];
__device__ double g_sums[3];   // [0]=sum|A|, [1]=sum(valid), [2]=sum(diff^2)

// ---------------------------------------------------------------------------
__device__ __forceinline__ float blockReduceSum(float v, float* sh) {
    int lane = threadIdx.x & 31;
    int wid  = threadIdx.x >> 5;
    #pragma unroll
    for (int o = 16; o > 0; o >>= 1) v += __shfl_down_sync(0xffffffffu, v, o);
    if (lane == 0) sh[wid] = v;
    __syncthreads();
    v = (threadIdx.x < 8) ? sh[threadIdx.x] : 0.f;
    if (wid == 0) {
        #pragma unroll
        for (int o = 4; o > 0; o >>= 1) v += __shfl_down_sync(0xffffffffu, v, o);
    }
    return v;
}

__device__ __forceinline__ void load_nbr24(const int* __restrict__ nbr,
                                           long long i, int* nn) {
    const int4* nb4 = (const int4*)(nbr + i * SS);
    #pragma unroll
    for (int k = 0; k < 6; k++) {
        int4 q = nb4[k];
        nn[4*k+0] = q.x; nn[4*k+1] = q.y; nn[4*k+2] = q.z; nn[4*k+3] = q.w;
    }
}

__device__ __forceinline__ void stage25(const float* __restrict__ src,
                                        int node0, float* sh_g, int tid) {
    const float* gBase = src + (long long)node0 * 25;
    #pragma unroll
    for (int k = 0; k < 25; k++) {
        int t = k * 256 + tid;
        sh_g[(t % 25) * PAD + t / 25] = gBase[t];
    }
}

// ---------------------------------------------------------------------------
// zero g_sums and g_u (float4 grid-stride; keeps g_u L2-resident for scatter)
__global__ __launch_bounds__(256) void k_zero() {
    long long i = (long long)blockIdx.x * blockDim.x + threadIdx.x;
    if (i == 0) { g_sums[0] = 0.0; g_sums[1] = 0.0; g_sums[2] = 0.0; }
    float4* u4 = (float4*)g_u;
    if (i < TOT / 4) u4[i] = make_float4(0.f, 0.f, 0.f, 0.f);
}

// K1 (atomic-bound only): wm = w*vm ; u += diag + G^T scatter (25 atomics/node)
__global__ __launch_bounds__(256) void k_scatter(const float* __restrict__ G,
                                                 const float* __restrict__ w,
                                                 const float* __restrict__ vm,
                                                 const int* __restrict__ nbr) {
    __shared__ float sh_g[25 * PAD];
    int tid = threadIdx.x;
    int node0 = blockIdx.x * 256;
    long long i = node0 + tid;
    int base = (i >= NN) ? NN : 0;

    stage25(G, node0, sh_g, tid);
    __syncthreads();

    float wmv = w[i] * vm[i];
    g_wm[i] = wmv;

    int nn[24];
    load_nbr24(nbr, i, nn);

    atomicAdd(&g_u[i], wmv * sh_g[tid]);              // diagonal
    #pragma unroll
    for (int j = 0; j < SS; j++) {
        int nb = nn[j];
        if ((unsigned)nb < (unsigned)NN)
            atomicAdd(&g_u[base + nb], wmv * sh_g[(j + 1) * PAD + tid]);
    }
}

// K2: v = G u + eps*wm  (+ flat |A| and valid reductions, streamed alongside)
__global__ __launch_bounds__(256) void k_gather_v(const float* __restrict__ G,
                                                  const float* __restrict__ Ad,
                                                  const float* __restrict__ Ao,
                                                  const float* __restrict__ vm,
                                                  const int* __restrict__ nbr) {
    __shared__ float sh_g[25 * PAD];
    __shared__ float sh_red[8];
    int tid = threadIdx.x;
    int node0 = blockIdx.x * 256;
    long long i = node0 + tid;
    int base = (i >= NN) ? NN : 0;

    stage25(G, node0, sh_g, tid);
    __syncthreads();

    int nn[24];
    load_nbr24(nbr, i, nn);
    float xs[24];
    #pragma unroll
    for (int j = 0; j < SS; j++)
        xs[j] = ((unsigned)nn[j] < (unsigned)NN) ? g_u[base + nn[j]] : 0.f;

    float acc = g_u[i] * sh_g[tid];
    #pragma unroll
    for (int j = 0; j < SS; j++)
        acc = fmaf(xs[j], sh_g[(j + 1) * PAD + tid], acc);

    g_v[i] = acc + EPSV * g_wm[i];

    // flat |A| partial (association-free bijection over Ao, coalesced float4)
    float s = fabsf(Ad[i]);
    const float4* A4 = (const float4*)Ao;             // TOT*6 float4 total
    #pragma unroll
    for (int k = 0; k < 6; k++) {
        float4 a = A4[(long long)k * TOT + i];
        s += fabsf(a.x) + fabsf(a.y) + fabsf(a.z) + fabsf(a.w);
    }
    float ba = blockReduceSum(s, sh_red);
    if (tid == 0) atomicAdd(&g_sums[0], (double)ba);
    __syncthreads();
    float bv = blockReduceSum(vm[i], sh_red);
    if (tid == 0) atomicAdd(&g_sums[1], (double)bv);
}

// K3: y = A v ; z = y/norm ; accumulate diff^2
__global__ __launch_bounds__(256) void k_gather_y(const float* __restrict__ Ad,
                                                  const float* __restrict__ Ao,
                                                  const float* __restrict__ vm,
                                                  const int* __restrict__ nbr) {
    __shared__ float sh_a[24 * PAD];
    __shared__ float sh_red[8];
    __shared__ float s_inv;
    int tid = threadIdx.x;
    int node0 = blockIdx.x * 256;
    long long i = node0 + tid;
    int base = (i >= NN) ? NN : 0;

    const float* aBase = Ao + (long long)node0 * SS;
    #pragma unroll
    for (int k = 0; k < 24; k++) {
        int t = k * 256 + tid;
        sh_a[(t % 24) * PAD + t / 24] = aBase[t];
    }
    if (tid == 0) {
        double norm = g_sums[0] / (g_sums[1] * 25.0 + 1e-6);
        s_inv = (float)(1.0 / (norm + 1e-8));
    }
    __syncthreads();

    int nn[24];
    load_nbr24(nbr, i, nn);
    float xs[24];
    #pragma unroll
    for (int j = 0; j < SS; j++)
        xs[j] = ((unsigned)nn[j] < (unsigned)NN) ? g_v[base + nn[j]] : 0.f;

    float acc = g_v[i] * Ad[i];
    #pragma unroll
    for (int j = 0; j < SS; j++)
        acc = fmaf(xs[j], sh_a[j * PAD + tid], acc);

    float z = acc * s_inv;
    float d = (z - g_wm[i]) * vm[i];
    float sred = blockReduceSum(d * d, sh_red);
    if (tid == 0) atomicAdd(&g_sums[2], (double)sred);
}

__global__ void k_final(float* out) {
    out[0] = (float)(g_sums[2] / (g_sums[1] + 1e-6));
}

// ---------------------------------------------------------------------------
extern "C" void kernel_launch(void* const* d_in, const int* in_sizes, int n_in,
                              void* d_out, int out_size) {
    const float* G   = (const float*)d_in[0];   // [2,N,25]
    const float* Ad  = (const float*)d_in[1];   // [2,N,1]
    const float* Ao  = (const float*)d_in[2];   // [2,N,24]
    const float* w   = (const float*)d_in[3];   // [2,N,1]
    const float* vm  = (const float*)d_in[4];   // [2,N,1]
    const int*   nbr = (const int*)d_in[5];     // [2,N,24] int32
    float* out = (float*)d_out;

    const int T = 256;
    const int nodeBlocks = TOT / T;             // 2048, exact
    const int zeroBlocks = TOT / 4 / T;         // 512

    k_zero    <<<zeroBlocks, T>>>();
    k_scatter <<<nodeBlocks, T>>>(G, w, vm, nbr);
    k_gather_v<<<nodeBlocks, T>>>(G, Ad, Ao, vm, nbr);
    k_gather_y<<<nodeBlocks, T>>>(Ad, Ao, vm, nbr);
    k_final   <<<1, 1>>>(out);
}

// round 9
// speedup vs baseline: 1.4452x; 1.0119x over previous
#include <cuda_runtime.h>

#define BB 2
#define NN 262144
#define SS 24
#define TOT (BB*NN)
#define EPSV 1e-4f

// ---- scratch (no allocation allowed; __device__ globals) ----
__device__ float g_wm[TOT];
__device__ float g_u[TOT];
__device__ float g_v[TOT];
__device__ double g_sums[3];   // [0]=sum|A|, [1]=sum(valid), [2]=sum(diff^2)

// ---------------------------------------------------------------------------
__device__ __forceinline__ float blockReduceSum(float v, float* sh) {
    int lane = threadIdx.x & 31;
    int wid  = threadIdx.x >> 5;
    #pragma unroll
    for (int o = 16; o > 0; o >>= 1) v += __shfl_down_sync(0xffffffffu, v, o);
    if (lane == 0) sh[wid] = v;
    __syncthreads();
    v = (threadIdx.x < 8) ? sh[threadIdx.x] : 0.f;
    if (wid == 0) {
        #pragma unroll
        for (int o = 4; o > 0; o >>= 1) v += __shfl_down_sync(0xffffffffu, v, o);
    }
    return v;
}

__device__ __forceinline__ void load_nbr24(const int* __restrict__ nbr,
                                           long long i, int* nn) {
    const int4* nb4 = (const int4*)(nbr + i * SS);
    #pragma unroll
    for (int k = 0; k < 6; k++) {
        int4 q = nb4[k];
        nn[4*k+0] = q.x; nn[4*k+1] = q.y; nn[4*k+2] = q.z; nn[4*k+3] = q.w;
    }
}

// Warp-private stage of 32 nodes x 25 G-coeffs (800 floats, linear copy).
// Read side: shw[lane*25 + c] — banks (25*lane+c)%32 conflict-free (25 coprime 32).
__device__ __forceinline__ void warp_stage_g25(const float* __restrict__ G,
                                               int warpNode0, float* shw, int lane) {
    const float* gBase = G + (long long)warpNode0 * 25;
    #pragma unroll
    for (int k = 0; k < 25; k++)
        shw[k * 32 + lane] = gBase[k * 32 + lane];
    __syncwarp();
}

// Warp-private stage of 32 nodes x 24 Ao-coeffs, padded row 24->25.
__device__ __forceinline__ void warp_stage_a24(const float* __restrict__ Ao,
                                               int warpNode0, float* shw, int lane) {
    const float* aBase = Ao + (long long)warpNode0 * SS;
    #pragma unroll
    for (int k = 0; k < 24; k++) {
        int e = k * 32 + lane;          // e = m*24 + c
        shw[e + e / 24] = aBase[e];     // -> m*25 + c
    }
    __syncwarp();
}

// ---------------------------------------------------------------------------
// zero g_sums and g_u (keeps g_u L2-resident for scatter)
__global__ __launch_bounds__(256) void k_zero() {
    long long i = (long long)blockIdx.x * blockDim.x + threadIdx.x;
    if (i == 0) { g_sums[0] = 0.0; g_sums[1] = 0.0; g_sums[2] = 0.0; }
    float4* u4 = (float4*)g_u;
    if (i < TOT / 4) u4[i] = make_float4(0.f, 0.f, 0.f, 0.f);
}

// K1: wm = w*vm ; u += diag + G^T scatter (25 atomics/node). Warp staging only.
__global__ __launch_bounds__(256) void k_scatter(const float* __restrict__ G,
                                                 const float* __restrict__ w,
                                                 const float* __restrict__ vm,
                                                 const int* __restrict__ nbr) {
    __shared__ float sh[8 * 800];
    int tid  = threadIdx.x;
    int lane = tid & 31;
    int wid  = tid >> 5;
    int node0 = blockIdx.x * 256;
    long long i = node0 + tid;
    int base = (i >= NN) ? NN : 0;
    float* shw = sh + wid * 800;

    warp_stage_g25(G, node0 + wid * 32, shw, lane);
    const float* my = shw + lane * 25;

    float wmv = w[i] * vm[i];
    g_wm[i] = wmv;

    int nn[24];
    load_nbr24(nbr, i, nn);

    atomicAdd(&g_u[i], wmv * my[0]);                  // diagonal (coalesced)
    #pragma unroll
    for (int j = 0; j < SS; j++) {
        int nb = nn[j];
        if ((unsigned)nb < (unsigned)NN)
            atomicAdd(&g_u[base + nb], wmv * my[1 + j]);
    }
}

// K2: v = G u + eps*wm (+ flat |A| and valid reductions, streamed alongside)
__global__ __launch_bounds__(256) void k_gather_v(const float* __restrict__ G,
                                                  const float* __restrict__ Ad,
                                                  const float* __restrict__ Ao,
                                                  const float* __restrict__ vm,
                                                  const int* __restrict__ nbr) {
    __shared__ float sh[8 * 800];
    __shared__ float sh_red[8];
    int tid  = threadIdx.x;
    int lane = tid & 31;
    int wid  = tid >> 5;
    int node0 = blockIdx.x * 256;
    long long i = node0 + tid;
    int base = (i >= NN) ? NN : 0;
    float* shw = sh + wid * 800;

    warp_stage_g25(G, node0 + wid * 32, shw, lane);
    const float* my = shw + lane * 25;

    int nn[24];
    load_nbr24(nbr, i, nn);
    float xs[24];
    #pragma unroll
    for (int j = 0; j < SS; j++)
        xs[j] = ((unsigned)nn[j] < (unsigned)NN) ? g_u[base + nn[j]] : 0.f;

    float acc = g_u[i] * my[0];
    #pragma unroll
    for (int j = 0; j < SS; j++)
        acc = fmaf(xs[j], my[1 + j], acc);

    g_v[i] = acc + EPSV * g_wm[i];

    // flat |A| partial (association-free bijection over Ao, coalesced float4)
    float s = fabsf(Ad[i]);
    const float4* A4 = (const float4*)Ao;             // TOT*6 float4 total
    #pragma unroll
    for (int k = 0; k < 6; k++) {
        float4 a = A4[(long long)k * TOT + i];
        s += fabsf(a.x) + fabsf(a.y) + fabsf(a.z) + fabsf(a.w);
    }
    float ba = blockReduceSum(s, sh_red);
    if (tid == 0) atomicAdd(&g_sums[0], (double)ba);
    __syncthreads();
    float bv = blockReduceSum(vm[i], sh_red);
    if (tid == 0) atomicAdd(&g_sums[1], (double)bv);
}

// K3: y = A v ; z = y/norm ; accumulate diff^2
__global__ __launch_bounds__(256) void k_gather_y(const float* __restrict__ Ad,
                                                  const float* __restrict__ Ao,
                                                  const float* __restrict__ vm,
                                                  const int* __restrict__ nbr) {
    __shared__ float sh[8 * 800];
    __shared__ float sh_red[8];
    int tid  = threadIdx.x;
    int lane = tid & 31;
    int wid  = tid >> 5;
    int node0 = blockIdx.x * 256;
    long long i = node0 + tid;
    int base = (i >= NN) ? NN : 0;
    float* shw = sh + wid * 800;

    warp_stage_a24(Ao, node0 + wid * 32, shw, lane);
    const float* my = shw + lane * 25;

    double norm = g_sums[0] / (g_sums[1] * 25.0 + 1e-6);
    float s_inv = (float)(1.0 / (norm + 1e-8));

    int nn[24];
    load_nbr24(nbr, i, nn);
    float xs[24];
    #pragma unroll
    for (int j = 0; j < SS; j++)
        xs[j] = ((unsigned)nn[j] < (unsigned)NN) ? g_v[base + nn[j]] : 0.f;

    float acc = g_v[i] * Ad[i];
    #pragma unroll
    for (int j = 0; j < SS; j++)
        acc = fmaf(xs[j], my[j], acc);

    float z = acc * s_inv;
    float d = (z - g_wm[i]) * vm[i];
    float sred = blockReduceSum(d * d, sh_red);
    if (tid == 0) atomicAdd(&g_sums[2], (double)sred);
}

__global__ void k_final(float* out) {
    out[0] = (float)(g_sums[2] / (g_sums[1] + 1e-6));
}

// ---------------------------------------------------------------------------
extern "C" void kernel_launch(void* const* d_in, const int* in_sizes, int n_in,
                              void* d_out, int out_size) {
    const float* G   = (const float*)d_in[0];   // [2,N,25]
    const float* Ad  = (const float*)d_in[1];   // [2,N,1]
    const float* Ao  = (const float*)d_in[2];   // [2,N,24]
    const float* w   = (const float*)d_in[3];   // [2,N,1]
    const float* vm  = (const float*)d_in[4];   // [2,N,1]
    const int*   nbr = (const int*)d_in[5];     // [2,N,24] int32
    float* out = (float*)d_out;

    const int T = 256;
    const int nodeBlocks = TOT / T;             // 2048, exact
    const int zeroBlocks = TOT / 4 / T;         // 512

    k_zero    <<<zeroBlocks, T>>>();
    k_scatter <<<nodeBlocks, T>>>(G, w, vm, nbr);
    k_gather_v<<<nodeBlocks, T>>>(G, Ad, Ao, vm, nbr);
    k_gather_y<<<nodeBlocks, T>>>(Ad, Ao, vm, nbr);
    k_final   <<<1, 1>>>(out);
}

// round 10
// speedup vs baseline: 1.4527x; 1.0052x over previous
#include <cuda_runtime.h>

#define BB 2
#define NN 262144
#define SS 24
#define TOT (BB*NN)
#define EPSV 1e-4f

// ---- scratch (no allocation allowed; __device__ globals) ----
__device__ float g_wm[TOT];
__device__ float g_u[TOT];
__device__ float g_v[TOT];
__device__ double g_sums[3];   // [0]=sum|A|, [1]=sum(valid), [2]=sum(diff^2)

// ---------------------------------------------------------------------------
__device__ __forceinline__ float blockReduceSum(float v, float* sh) {
    int lane = threadIdx.x & 31;
    int wid  = threadIdx.x >> 5;
    #pragma unroll
    for (int o = 16; o > 0; o >>= 1) v += __shfl_down_sync(0xffffffffu, v, o);
    if (lane == 0) sh[wid] = v;
    __syncthreads();
    v = (threadIdx.x < 8) ? sh[threadIdx.x] : 0.f;
    if (wid == 0) {
        #pragma unroll
        for (int o = 4; o > 0; o >>= 1) v += __shfl_down_sync(0xffffffffu, v, o);
    }
    return v;
}

__device__ __forceinline__ void load_nbr24(const int* __restrict__ nbr,
                                           long long i, int* nn) {
    const int4* nb4 = (const int4*)(nbr + i * SS);
    #pragma unroll
    for (int k = 0; k < 6; k++) {
        int4 q = nb4[k];
        nn[4*k+0] = q.x; nn[4*k+1] = q.y; nn[4*k+2] = q.z; nn[4*k+3] = q.w;
    }
}

// Warp-private stage of 32 nodes x 25 G-coeffs (800 floats, linear copy).
// Read side: shw[lane*25 + c] — banks (25*lane+c)%32 conflict-free (25 coprime 32).
__device__ __forceinline__ void warp_stage_g25(const float* __restrict__ G,
                                               int warpNode0, float* shw, int lane) {
    const float* gBase = G + (long long)warpNode0 * 25;
    #pragma unroll
    for (int k = 0; k < 25; k++)
        shw[k * 32 + lane] = gBase[k * 32 + lane];
    __syncwarp();
}

// Warp-private stage of 32 nodes x 24 Ao-coeffs, padded row 24->25.
__device__ __forceinline__ void warp_stage_a24(const float* __restrict__ Ao,
                                               int warpNode0, float* shw, int lane) {
    const float* aBase = Ao + (long long)warpNode0 * SS;
    #pragma unroll
    for (int k = 0; k < 24; k++) {
        int e = k * 32 + lane;          // e = m*24 + c
        shw[e + e / 24] = aBase[e];     // -> m*25 + c
    }
    __syncwarp();
}

// ---------------------------------------------------------------------------
// zero g_sums and g_u (keeps g_u L2-resident for scatter)
__global__ __launch_bounds__(256) void k_zero() {
    long long i = (long long)blockIdx.x * blockDim.x + threadIdx.x;
    if (i == 0) { g_sums[0] = 0.0; g_sums[1] = 0.0; g_sums[2] = 0.0; }
    float4* u4 = (float4*)g_u;
    if (i < TOT / 4) u4[i] = make_float4(0.f, 0.f, 0.f, 0.f);
}

// K1: wm = w*vm ; u += diag + G^T scatter (25 atomics/node). Warp staging only.
__global__ __launch_bounds__(256) void k_scatter(const float* __restrict__ G,
                                                 const float* __restrict__ w,
                                                 const float* __restrict__ vm,
                                                 const int* __restrict__ nbr) {
    __shared__ float sh[8 * 800];
    int tid  = threadIdx.x;
    int lane = tid & 31;
    int wid  = tid >> 5;
    int node0 = blockIdx.x * 256;
    long long i = node0 + tid;
    int base = (i >= NN) ? NN : 0;
    float* shw = sh + wid * 800;

    warp_stage_g25(G, node0 + wid * 32, shw, lane);
    const float* my = shw + lane * 25;

    float wmv = w[i] * vm[i];
    g_wm[i] = wmv;

    int nn[24];
    load_nbr24(nbr, i, nn);

    atomicAdd(&g_u[i], wmv * my[0]);                  // diagonal (coalesced)
    #pragma unroll
    for (int j = 0; j < SS; j++) {
        int nb = nn[j];
        if ((unsigned)nb < (unsigned)NN)
            atomicAdd(&g_u[base + nb], wmv * my[1 + j]);
    }
}

// K2: v = G u + eps*wm (+ flat |A| and valid reductions, streamed alongside)
__global__ __launch_bounds__(256) void k_gather_v(const float* __restrict__ G,
                                                  const float* __restrict__ Ad,
                                                  const float* __restrict__ Ao,
                                                  const float* __restrict__ vm,
                                                  const int* __restrict__ nbr) {
    __shared__ float sh[8 * 800];
    __shared__ float sh_red[8];
    int tid  = threadIdx.x;
    int lane = tid & 31;
    int wid  = tid >> 5;
    int node0 = blockIdx.x * 256;
    long long i = node0 + tid;
    int base = (i >= NN) ? NN : 0;
    float* shw = sh + wid * 800;

    warp_stage_g25(G, node0 + wid * 32, shw, lane);
    const float* my = shw + lane * 25;

    int nn[24];
    load_nbr24(nbr, i, nn);
    float xs[24];
    #pragma unroll
    for (int j = 0; j < SS; j++)
        xs[j] = ((unsigned)nn[j] < (unsigned)NN) ? g_u[base + nn[j]] : 0.f;

    float acc = g_u[i] * my[0];
    #pragma unroll
    for (int j = 0; j < SS; j++)
        acc = fmaf(xs[j], my[1 + j], acc);

    g_v[i] = acc + EPSV * g_wm[i];

    // flat |A| partial (association-free bijection over Ao, coalesced float4)
    float s = fabsf(Ad[i]);
    const float4* A4 = (const float4*)Ao;             // TOT*6 float4 total
    #pragma unroll
    for (int k = 0; k < 6; k++) {
        float4 a = A4[(long long)k * TOT + i];
        s += fabsf(a.x) + fabsf(a.y) + fabsf(a.z) + fabsf(a.w);
    }
    float ba = blockReduceSum(s, sh_red);
    if (tid == 0) atomicAdd(&g_sums[0], (double)ba);
    __syncthreads();
    float bv = blockReduceSum(vm[i], sh_red);
    if (tid == 0) atomicAdd(&g_sums[1], (double)bv);
}

// K3: y = A v ; z = y/norm ; accumulate diff^2.
// s_inv computed ONCE per warp (lane 0) and shfl-broadcast — no per-thread DP.
__global__ __launch_bounds__(256) void k_gather_y(const float* __restrict__ Ad,
                                                  const float* __restrict__ Ao,
                                                  const float* __restrict__ vm,
                                                  const int* __restrict__ nbr) {
    __shared__ float sh[8 * 800];
    __shared__ float sh_red[8];
    int tid  = threadIdx.x;
    int lane = tid & 31;
    int wid  = tid >> 5;
    int node0 = blockIdx.x * 256;
    long long i = node0 + tid;
    int base = (i >= NN) ? NN : 0;
    float* shw = sh + wid * 800;

    warp_stage_a24(Ao, node0 + wid * 32, shw, lane);
    const float* my = shw + lane * 25;

    float s_inv = 0.f;
    if (lane == 0) {
        double norm = g_sums[0] / (g_sums[1] * 25.0 + 1e-6);
        s_inv = (float)(1.0 / (norm + 1e-8));
    }
    s_inv = __shfl_sync(0xffffffffu, s_inv, 0);

    int nn[24];
    load_nbr24(nbr, i, nn);
    float xs[24];
    #pragma unroll
    for (int j = 0; j < SS; j++)
        xs[j] = ((unsigned)nn[j] < (unsigned)NN) ? g_v[base + nn[j]] : 0.f;

    float acc = g_v[i] * Ad[i];
    #pragma unroll
    for (int j = 0; j < SS; j++)
        acc = fmaf(xs[j], my[j], acc);

    float z = acc * s_inv;
    float d = (z - g_wm[i]) * vm[i];
    float sred = blockReduceSum(d * d, sh_red);
    if (tid == 0) atomicAdd(&g_sums[2], (double)sred);
}

__global__ void k_final(float* out) {
    out[0] = (float)(g_sums[2] / (g_sums[1] + 1e-6));
}

// ---------------------------------------------------------------------------
extern "C" void kernel_launch(void* const* d_in, const int* in_sizes, int n_in,
                              void* d_out, int out_size) {
    const float* G   = (const float*)d_in[0];   // [2,N,25]
    const float* Ad  = (const float*)d_in[1];   // [2,N,1]
    const float* Ao  = (const float*)d_in[2];   // [2,N,24]
    const float* w   = (const float*)d_in[3];   // [2,N,1]
    const float* vm  = (const float*)d_in[4];   // [2,N,1]
    const int*   nbr = (const int*)d_in[5];     // [2,N,24] int32
    float* out = (float*)d_out;

    const int T = 256;
    const int nodeBlocks = TOT / T;             // 2048, exact
    const int zeroBlocks = TOT / 4 / T;         // 512

    k_zero    <<<zeroBlocks, T>>>();
    k_scatter <<<nodeBlocks, T>>>(G, w, vm, nbr);
    k_gather_v<<<nodeBlocks, T>>>(G, Ad, Ao, vm, nbr);
    k_gather_y<<<nodeBlocks, T>>>(Ad, Ao, vm, nbr);
    k_final   <<<1, 1>>>(out);
}

// round 11
// speedup vs baseline: 1.4646x; 1.0082x over previous
#include <cuda_runtime.h>

#define BB 2
#define NN 262144
#define SS 24
#define TOT (BB*NN)
#define EPSV 1e-4f
#define NPART 64

// ---- scratch (no allocation allowed; __device__ globals) ----
__device__ float  g_wm[TOT];
__device__ float  g_u[TOT];
__device__ float  g_v[TOT];
__device__ double g_partA[NPART];   // |A| partials
__device__ double g_partV[NPART];   // valid partials
__device__ double g_partD[NPART];   // diff^2 partials
__device__ float  g_sinv;           // 1/(norm+1e-8), set by k_norm
__device__ double g_validsum;       // sum(valid), set by k_norm

// ---------------------------------------------------------------------------
__device__ __forceinline__ float warpReduceSum(float v) {
    #pragma unroll
    for (int o = 16; o > 0; o >>= 1) v += __shfl_down_sync(0xffffffffu, v, o);
    return v;
}

__device__ __forceinline__ void load_nbr24(const int* __restrict__ nbr,
                                           long long i, int* nn) {
    const int4* nb4 = (const int4*)(nbr + i * SS);
    #pragma unroll
    for (int k = 0; k < 6; k++) {
        int4 q = nb4[k];
        nn[4*k+0] = q.x; nn[4*k+1] = q.y; nn[4*k+2] = q.z; nn[4*k+3] = q.w;
    }
}

// Warp-private stage of 32 nodes x 25 G-coeffs (800 floats, linear copy).
__device__ __forceinline__ void warp_stage_g25(const float* __restrict__ G,
                                               int warpNode0, float* shw, int lane) {
    const float* gBase = G + (long long)warpNode0 * 25;
    #pragma unroll
    for (int k = 0; k < 25; k++)
        shw[k * 32 + lane] = gBase[k * 32 + lane];
    __syncwarp();
}

// Warp-private stage of 32 nodes x 24 Ao-coeffs, padded row 24->25.
__device__ __forceinline__ void warp_stage_a24(const float* __restrict__ Ao,
                                               int warpNode0, float* shw, int lane) {
    const float* aBase = Ao + (long long)warpNode0 * SS;
    #pragma unroll
    for (int k = 0; k < 24; k++) {
        int e = k * 32 + lane;          // e = m*24 + c
        shw[e + e / 24] = aBase[e];     // -> m*25 + c
    }
    __syncwarp();
}

// ---------------------------------------------------------------------------
// zero g_u and partial arrays (keeps g_u L2-resident for scatter)
__global__ __launch_bounds__(256) void k_zero() {
    long long i = (long long)blockIdx.x * blockDim.x + threadIdx.x;
    if (i < NPART) { g_partA[i] = 0.0; g_partV[i] = 0.0; g_partD[i] = 0.0; }
    float4* u4 = (float4*)g_u;
    if (i < TOT / 4) u4[i] = make_float4(0.f, 0.f, 0.f, 0.f);
}

// K1: wm = w*vm ; u += diag + G^T scatter (25 atomics/node). No barriers.
__global__ __launch_bounds__(256) void k_scatter(const float* __restrict__ G,
                                                 const float* __restrict__ w,
                                                 const float* __restrict__ vm,
                                                 const int* __restrict__ nbr) {
    __shared__ float sh[8 * 800];
    int tid  = threadIdx.x;
    int lane = tid & 31;
    int wid  = tid >> 5;
    int node0 = blockIdx.x * 256;
    long long i = node0 + tid;
    int base = (i >= NN) ? NN : 0;
    float* shw = sh + wid * 800;

    warp_stage_g25(G, node0 + wid * 32, shw, lane);
    const float* my = shw + lane * 25;

    float wmv = w[i] * vm[i];
    g_wm[i] = wmv;

    int nn[24];
    load_nbr24(nbr, i, nn);

    atomicAdd(&g_u[i], wmv * my[0]);                  // diagonal (coalesced)
    #pragma unroll
    for (int j = 0; j < SS; j++) {
        int nb = nn[j];
        if ((unsigned)nb < (unsigned)NN)
            atomicAdd(&g_u[base + nb], wmv * my[1 + j]);
    }
}

// K2: v = G u + eps*wm (+ |A| and valid warp-partials). Barrier-free.
__global__ __launch_bounds__(256) void k_gather_v(const float* __restrict__ G,
                                                  const float* __restrict__ Ad,
                                                  const float* __restrict__ Ao,
                                                  const float* __restrict__ vm,
                                                  const int* __restrict__ nbr) {
    __shared__ float sh[8 * 800];
    int tid  = threadIdx.x;
    int lane = tid & 31;
    int wid  = tid >> 5;
    int node0 = blockIdx.x * 256;
    long long i = node0 + tid;
    int base = (i >= NN) ? NN : 0;
    float* shw = sh + wid * 800;

    warp_stage_g25(G, node0 + wid * 32, shw, lane);
    const float* my = shw + lane * 25;

    int nn[24];
    load_nbr24(nbr, i, nn);
    float xs[24];
    #pragma unroll
    for (int j = 0; j < SS; j++)
        xs[j] = ((unsigned)nn[j] < (unsigned)NN) ? g_u[base + nn[j]] : 0.f;

    float acc = g_u[i] * my[0];
    #pragma unroll
    for (int j = 0; j < SS; j++)
        acc = fmaf(xs[j], my[1 + j], acc);

    g_v[i] = acc + EPSV * g_wm[i];

    // flat |A| partial (association-free bijection over Ao, coalesced float4)
    float v = vm[i];
    float s = fabsf(Ad[i]);
    const float4* A4 = (const float4*)Ao;             // TOT*6 float4 total
    #pragma unroll
    for (int k = 0; k < 6; k++) {
        float4 a = A4[(long long)k * TOT + i];
        s += fabsf(a.x) + fabsf(a.y) + fabsf(a.z) + fabsf(a.w);
    }
    float ws = warpReduceSum(s);
    float wv = warpReduceSum(v);
    if (lane == 0) {
        int slot = (blockIdx.x * 8 + wid) & (NPART - 1);
        atomicAdd(&g_partA[slot], (double)ws);
        atomicAdd(&g_partV[slot], (double)wv);
    }
}

// Tiny: reduce partials -> s_inv (and stash valid sum for k_final)
__global__ void k_norm() {
    int t = threadIdx.x;                // 64 threads
    double a = g_partA[t];
    double v = g_partV[t];
    #pragma unroll
    for (int o = 16; o > 0; o >>= 1) {
        a += __shfl_down_sync(0xffffffffu, a, o);
        v += __shfl_down_sync(0xffffffffu, v, o);
    }
    __shared__ double shA[2], shV[2];
    if ((t & 31) == 0) { shA[t >> 5] = a; shV[t >> 5] = v; }
    __syncthreads();
    if (t == 0) {
        double A = shA[0] + shA[1];
        double V = shV[0] + shV[1];
        double norm = A / (V * 25.0 + 1e-6);
        g_sinv = (float)(1.0 / (norm + 1e-8));
        g_validsum = V;
    }
}

// K3: y = A v ; z = y*s_inv ; diff^2 warp-partials. Barrier-free, no DP.
__global__ __launch_bounds__(256) void k_gather_y(const float* __restrict__ Ad,
                                                  const float* __restrict__ Ao,
                                                  const float* __restrict__ vm,
                                                  const int* __restrict__ nbr) {
    __shared__ float sh[8 * 800];
    int tid  = threadIdx.x;
    int lane = tid & 31;
    int wid  = tid >> 5;
    int node0 = blockIdx.x * 256;
    long long i = node0 + tid;
    int base = (i >= NN) ? NN : 0;
    float* shw = sh + wid * 800;

    warp_stage_a24(Ao, node0 + wid * 32, shw, lane);
    const float* my = shw + lane * 25;

    float s_inv = g_sinv;               // uniform scalar load

    int nn[24];
    load_nbr24(nbr, i, nn);
    float xs[24];
    #pragma unroll
    for (int j = 0; j < SS; j++)
        xs[j] = ((unsigned)nn[j] < (unsigned)NN) ? g_v[base + nn[j]] : 0.f;

    float acc = g_v[i] * Ad[i];
    #pragma unroll
    for (int j = 0; j < SS; j++)
        acc = fmaf(xs[j], my[j], acc);

    float z = acc * s_inv;
    float d = (z - g_wm[i]) * vm[i];
    float wd = warpReduceSum(d * d);
    if (lane == 0) {
        int slot = (blockIdx.x * 8 + wid) & (NPART - 1);
        atomicAdd(&g_partD[slot], (double)wd);
    }
}

__global__ void k_final(float* out) {
    int t = threadIdx.x;                // 64 threads
    double d = g_partD[t];
    #pragma unroll
    for (int o = 16; o > 0; o >>= 1)
        d += __shfl_down_sync(0xffffffffu, d, o);
    __shared__ double shD[2];
    if ((t & 31) == 0) shD[t >> 5] = d;
    __syncthreads();
    if (t == 0)
        out[0] = (float)((shD[0] + shD[1]) / (g_validsum + 1e-6));
}

// ---------------------------------------------------------------------------
extern "C" void kernel_launch(void* const* d_in, const int* in_sizes, int n_in,
                              void* d_out, int out_size) {
    const float* G   = (const float*)d_in[0];   // [2,N,25]
    const float* Ad  = (const float*)d_in[1];   // [2,N,1]
    const float* Ao  = (const float*)d_in[2];   // [2,N,24]
    const float* w   = (const float*)d_in[3];   // [2,N,1]
    const float* vm  = (const float*)d_in[4];   // [2,N,1]
    const int*   nbr = (const int*)d_in[5];     // [2,N,24] int32
    float* out = (float*)d_out;

    const int T = 256;
    const int nodeBlocks = TOT / T;             // 2048, exact
    const int zeroBlocks = TOT / 4 / T;         // 512

    k_zero    <<<zeroBlocks, T>>>();
    k_scatter <<<nodeBlocks, T>>>(G, w, vm, nbr);
    k_gather_v<<<nodeBlocks, T>>>(G, Ad, Ao, vm, nbr);
    k_norm    <<<1, 64>>>();
    k_gather_y<<<nodeBlocks, T>>>(Ad, Ao, vm, nbr);
    k_final   <<<1, 64>>>(out);
}